// round 1
// baseline (speedup 1.0000x reference)
#include <cuda_runtime.h>

#define BATCH 64
#define NNODE 27
#define CDIM  512
#define NNSQ  729
#define NROWS_X (BATCH*NNODE)   // 1728
#define SSTR 520                // staging row stride (floats)

// ---- scratch (no allocs allowed) ----
__device__ float g_Vix[NROWS_X*CDIM];
__device__ float g_Vjx[NROWS_X*CDIM];
__device__ float g_Ujx[NROWS_X*CDIM];
__device__ float g_XU [NROWS_X*CDIM];
__device__ float g_agg[NROWS_X*CDIM];

// ============================================================
// K1: node projections  out = x @ W  for WA,WB,WV,WU
// block: 32 rows x 512 cols, 256 threads, 8x8 thread tile, k-tile 16
// ============================================================
__global__ __launch_bounds__(256, 2)
void node_gemm(const float* __restrict__ x,
               const float* __restrict__ WA, const float* __restrict__ WB,
               const float* __restrict__ WV, const float* __restrict__ WU)
{
    __shared__ float sW[16*512];
    __shared__ float sA[16*32];
    const int tid = threadIdx.x;
    const int rowBase = blockIdx.x * 32;
    const float* W; float* out;
    switch (blockIdx.y) {
        case 0: W = WA; out = g_Vix; break;
        case 1: W = WB; out = g_Vjx; break;
        case 2: W = WV; out = g_Ujx; break;
        default: W = WU; out = g_XU; break;
    }
    const int cg = tid & 63;
    const int rg = tid >> 6;

    float acc[8][8];
#pragma unroll
    for (int a = 0; a < 8; a++)
#pragma unroll
        for (int b = 0; b < 8; b++) acc[a][b] = 0.f;

    for (int kt = 0; kt < 512; kt += 16) {
        __syncthreads();
#pragma unroll
        for (int l = 0; l < 8; l++) {
            int f  = tid + l*256;       // float4 slot 0..2047
            int k  = f >> 7;
            int c4 = f & 127;
            *(float4*)&sW[k*512 + c4*4] = *(const float4*)&W[(kt+k)*512 + c4*4];
        }
        if (tid < 128) {
            int j = tid >> 2, q = tid & 3;
            float4 v = *(const float4*)&x[(size_t)(rowBase + j)*512 + kt + q*4];
            sA[(q*4+0)*32 + j] = v.x;
            sA[(q*4+1)*32 + j] = v.y;
            sA[(q*4+2)*32 + j] = v.z;
            sA[(q*4+3)*32 + j] = v.w;
        }
        __syncthreads();
#pragma unroll
        for (int k = 0; k < 16; k++) {
            float4 w0 = *(float4*)&sW[k*512 + cg*4];
            float4 w1 = *(float4*)&sW[k*512 + 256 + cg*4];
            float4 e0 = *(float4*)&sA[k*32 + rg*4];
            float4 e1 = *(float4*)&sA[k*32 + 16 + rg*4];
            float ev[8] = {e0.x,e0.y,e0.z,e0.w,e1.x,e1.y,e1.z,e1.w};
            float wv[8] = {w0.x,w0.y,w0.z,w0.w,w1.x,w1.y,w1.z,w1.w};
#pragma unroll
            for (int a = 0; a < 8; a++)
#pragma unroll
                for (int b = 0; b < 8; b++)
                    acc[a][b] += ev[a]*wv[b];
        }
    }
#pragma unroll
    for (int a = 0; a < 8; a++) {
        int row = rowBase + (a < 4 ? rg*4 + a : 16 + rg*4 + (a-4));
        float4 v0 = {acc[a][0],acc[a][1],acc[a][2],acc[a][3]};
        float4 v1 = {acc[a][4],acc[a][5],acc[a][6],acc[a][7]};
        *(float4*)&out[(size_t)row*512 + cg*4]       = v0;
        *(float4*)&out[(size_t)row*512 + 256 + cg*4] = v1;
    }
}

// ============================================================
// K2: fused edge pipeline. One CTA per (b,i): 27 edge rows.
//   e_lin = edge[27x512] @ WE   (GEMM, 27 padded to 32)
//   t = e_lin + Vix[i] + Vjx[j]; LN rows; relu; edge_out = edge + .
//   s = sigmoid(edge_out); softmax over j; agg = sum_j e*Ujx[j]/27
// smem: union{ GEMM tiles (8704 f) , staging 32x520 (16640 f) } + Vix/ge/be rows
// ============================================================
__global__ __launch_bounds__(256, 2)
void edge_kernel(const float* __restrict__ edge, const float* __restrict__ WE,
                 const float* __restrict__ ge, const float* __restrict__ be,
                 float* __restrict__ edge_out)
{
    extern __shared__ float sm[];
    float* sW   = sm;              // [16][512]   (GEMM phase)
    float* sE   = sm + 16*512;     // [16][32]    (GEMM phase)
    float* sS   = sm;              // [32][520]   (epilogue staging, aliases tiles)
    float* sVix = sm + 16640;      // [512]
    float* sGe  = sm + 16640 + 512;
    float* sBe  = sm + 16640 + 1024;

    const int tid = threadIdx.x;
    const int bi  = blockIdx.x;
    const int b   = bi / NNODE;
    const int i   = bi % NNODE;
    const size_t rowBaseE = (size_t)b*NNSQ + (size_t)i*NNODE;
    const float* eBase = edge + rowBaseE*CDIM;

    { // preload Vix row i, gamma, beta (region disjoint from GEMM tiles)
        const float* vix = g_Vix + ((size_t)b*NNODE + i)*CDIM;
        int c0 = tid, c1 = tid + 256;
        sVix[c0] = vix[c0]; sVix[c1] = vix[c1];
        sGe[c0]  = ge[c0];  sGe[c1]  = ge[c1];
        sBe[c0]  = be[c0];  sBe[c1]  = be[c1];
    }

    const int cg = tid & 63;
    const int rg = tid >> 6;

    float acc[8][8];
#pragma unroll
    for (int a = 0; a < 8; a++)
#pragma unroll
        for (int c = 0; c < 8; c++) acc[a][c] = 0.f;

    for (int kt = 0; kt < 512; kt += 16) {
        __syncthreads();
#pragma unroll
        for (int l = 0; l < 8; l++) {
            int f  = tid + l*256;
            int k  = f >> 7;
            int c4 = f & 127;
            *(float4*)&sW[k*512 + c4*4] = *(const float4*)&WE[(kt+k)*512 + c4*4];
        }
        if (tid < 128) {
            int j = tid >> 2, q = tid & 3;
            float4 v = make_float4(0.f,0.f,0.f,0.f);
            if (j < NNODE) v = *(const float4*)&eBase[(size_t)j*512 + kt + q*4];
            sE[(q*4+0)*32 + j] = v.x;
            sE[(q*4+1)*32 + j] = v.y;
            sE[(q*4+2)*32 + j] = v.z;
            sE[(q*4+3)*32 + j] = v.w;
        }
        __syncthreads();
#pragma unroll
        for (int k = 0; k < 16; k++) {
            float4 w0 = *(float4*)&sW[k*512 + cg*4];
            float4 w1 = *(float4*)&sW[k*512 + 256 + cg*4];
            float4 e0 = *(float4*)&sE[k*32 + rg*4];
            float4 e1 = *(float4*)&sE[k*32 + 16 + rg*4];
            float ev[8] = {e0.x,e0.y,e0.z,e0.w,e1.x,e1.y,e1.z,e1.w};
            float wv[8] = {w0.x,w0.y,w0.z,w0.w,w1.x,w1.y,w1.z,w1.w};
#pragma unroll
            for (int a = 0; a < 8; a++)
#pragma unroll
                for (int c = 0; c < 8; c++)
                    acc[a][c] += ev[a]*wv[c];
        }
    }

    // stage accumulators into sS (aliases GEMM tiles -> sync first)
    __syncthreads();
#pragma unroll
    for (int a = 0; a < 8; a++) {
        int row = (a < 4 ? rg*4 + a : 16 + rg*4 + (a-4));
        float4 v0 = {acc[a][0],acc[a][1],acc[a][2],acc[a][3]};
        float4 v1 = {acc[a][4],acc[a][5],acc[a][6],acc[a][7]};
        *(float4*)&sS[row*SSTR + cg*4]       = v0;
        *(float4*)&sS[row*SSTR + 256 + cg*4] = v1;
    }
    __syncthreads();

    // Phase A (row mode): msg add + LayerNorm + relu + residual + sigmoid stage
    const int lane = tid & 31, wrp = tid >> 5;
    for (int r = wrp; r < NNODE; r += 8) {
        const float* vjx = g_Vjx + ((size_t)b*NNODE + r)*CDIM;
        float v[16]; float s = 0.f, s2 = 0.f;
#pragma unroll
        for (int u = 0; u < 16; u++) {
            int c = lane + u*32;
            float t = sS[r*SSTR + c] + sVix[c] + vjx[c];
            v[u] = t; s += t; s2 += t*t;
        }
#pragma unroll
        for (int o = 16; o > 0; o >>= 1) {
            s  += __shfl_xor_sync(0xffffffffu, s,  o);
            s2 += __shfl_xor_sync(0xffffffffu, s2, o);
        }
        float mean = s * (1.f/512.f);
        float var  = s2 * (1.f/512.f) - mean*mean;
        float rstd = rsqrtf(var + 1e-5f);
        const float* eRow = eBase + (size_t)r*CDIM;
        float* oRow = edge_out + (rowBaseE + r)*CDIM;
#pragma unroll
        for (int u = 0; u < 16; u++) {
            int c = lane + u*32;
            float ln = (v[u] - mean)*rstd*sGe[c] + sBe[c];
            float eo = eRow[c] + fmaxf(ln, 0.f);
            oRow[c] = eo;
            sS[r*SSTR + c] = 1.f/(1.f + __expf(-eo));
        }
    }
    __syncthreads();

    // Phase B (column mode): softmax over j (27 rows) + gated aggregation
    float* aggRow = g_agg + ((size_t)b*NNODE + i)*CDIM;
#pragma unroll
    for (int h = 0; h < 2; h++) {
        int c = tid + h*256;
        float sum = 0.f, a = 0.f;
#pragma unroll
        for (int j = 0; j < NNODE; j++) {
            float ex = __expf(sS[j*SSTR + c]);
            sum += ex;
            a   += ex * g_Ujx[((size_t)b*NNODE + j)*CDIM + c];
        }
        aggRow[c] = a / (sum * (float)NNODE);
    }
}

// ============================================================
// K3: x_new = XU + agg; x_out = relu(x + LN(x_new, gv, bv))
// one CTA (256 thr) per node row
// ============================================================
__global__ void node_finalize(const float* __restrict__ x,
                              const float* __restrict__ gv, const float* __restrict__ bv,
                              float* __restrict__ x_out)
{
    __shared__ float rs[8], rs2[8];
    __shared__ float bmean, brstd;
    const int row = blockIdx.x;
    const int tid = threadIdx.x;
    const int lane = tid & 31, wrp = tid >> 5;
    const size_t base = (size_t)row*CDIM;

    float t0 = g_XU[base + tid]       + g_agg[base + tid];
    float t1 = g_XU[base + 256 + tid] + g_agg[base + 256 + tid];
    float s = t0 + t1, s2 = t0*t0 + t1*t1;
#pragma unroll
    for (int o = 16; o > 0; o >>= 1) {
        s  += __shfl_xor_sync(0xffffffffu, s,  o);
        s2 += __shfl_xor_sync(0xffffffffu, s2, o);
    }
    if (lane == 0) { rs[wrp] = s; rs2[wrp] = s2; }
    __syncthreads();
    if (tid == 0) {
        float S = 0.f, S2 = 0.f;
#pragma unroll
        for (int k = 0; k < 8; k++) { S += rs[k]; S2 += rs2[k]; }
        float mean = S * (1.f/512.f);
        float var  = S2 * (1.f/512.f) - mean*mean;
        bmean = mean; brstd = rsqrtf(var + 1e-5f);
    }
    __syncthreads();
    float mean = bmean, rstd = brstd;
    int c0 = tid, c1 = tid + 256;
    float ln0 = (t0 - mean)*rstd*gv[c0] + bv[c0];
    float ln1 = (t1 - mean)*rstd*gv[c1] + bv[c1];
    x_out[base + c0] = fmaxf(x[base + c0] + ln0, 0.f);
    x_out[base + c1] = fmaxf(x[base + c1] + ln1, 0.f);
}

// ============================================================
extern "C" void kernel_launch(void* const* d_in, const int* in_sizes, int n_in,
                              void* d_out, int out_size)
{
    const float* x    = (const float*)d_in[0];
    const float* edge = (const float*)d_in[1];
    const float* WA   = (const float*)d_in[2];
    const float* WB   = (const float*)d_in[3];
    const float* WE   = (const float*)d_in[4];
    const float* WU   = (const float*)d_in[5];
    const float* WV   = (const float*)d_in[6];
    const float* gv   = (const float*)d_in[7];
    const float* bv   = (const float*)d_in[8];
    const float* ge   = (const float*)d_in[9];
    const float* be   = (const float*)d_in[10];

    float* x_out = (float*)d_out;                              // (64,27,512) first
    float* e_out = (float*)d_out + (size_t)NROWS_X*CDIM;       // (64,729,512) second

    const int smemK2 = (16640 + 1536) * (int)sizeof(float);    // 72704 B
    cudaFuncSetAttribute(edge_kernel, cudaFuncAttributeMaxDynamicSharedMemorySize, smemK2);

    node_gemm<<<dim3(54, 4), 256>>>(x, WA, WB, WV, WU);
    edge_kernel<<<BATCH*NNODE, 256, smemK2>>>(edge, WE, ge, be, e_out);
    node_finalize<<<NROWS_X, 256>>>(x, gv, bv, x_out);
}

// round 3
// speedup vs baseline: 1.6730x; 1.6730x over previous
#include <cuda_runtime.h>
#include <cuda_bf16.h>
#include <cstdint>

#define BATCH 64
#define NNODE 27
#define CDIM  512
#define NNSQ  729
#define NROWS_X (BATCH*NNODE)      // 1728
#define NROWS_E (BATCH*NNSQ)       // 46656
#define SSTR 520

#define BM 128
#define BN 128
#define BK 32
#define SROWB 80                    // smem row stride bytes (40 bf16)
#define ARR_BYTES 10240             // 128 rows * 80B
#define STAGE_BYTES 40960           // Ah|Al|Bh|Bl
#define SMEM_GEMM (2*STAGE_BYTES)   // 81920

// ------------------------------------------------------------------
// scratch (device globals; allocs are forbidden)
// ------------------------------------------------------------------
__device__ float g_elin[(size_t)NROWS_E*CDIM];
__device__ float g_node[(size_t)NROWS_X*2048];          // Vix|Vjx|Ujx|XU
__device__ float g_agg [(size_t)NROWS_X*CDIM];
__device__ __nv_bfloat16 g_eAh[(size_t)NROWS_E*CDIM];
__device__ __nv_bfloat16 g_eAl[(size_t)NROWS_E*CDIM];
__device__ __nv_bfloat16 g_xAh[(size_t)NROWS_X*CDIM];
__device__ __nv_bfloat16 g_xAl[(size_t)NROWS_X*CDIM];
__device__ __nv_bfloat16 g_WEth[512*512];
__device__ __nv_bfloat16 g_WEtl[512*512];
__device__ __nv_bfloat16 g_Wcth[2048*512];
__device__ __nv_bfloat16 g_Wctl[2048*512];

// ------------------------------------------------------------------
// helpers (compute_100-safe: cp.async / ldmatrix / mma.sync only)
// ------------------------------------------------------------------
__device__ __forceinline__ uint32_t smem_to_u32(const void* p) {
    uint32_t a;
    asm("{ .reg .u64 t; cvta.to.shared.u64 t, %1; cvt.u32.u64 %0, t; }" : "=r"(a) : "l"(p));
    return a;
}
__device__ __forceinline__ void cp_async16(uint32_t dst, const void* src, bool pred) {
    int sz = pred ? 16 : 0;
    asm volatile("cp.async.cg.shared.global [%0], [%1], 16, %2;"
                 :: "r"(dst), "l"(src), "r"(sz) : "memory");
}
__device__ __forceinline__ void ldsm4(uint32_t& r0, uint32_t& r1, uint32_t& r2, uint32_t& r3,
                                      uint32_t addr) {
    asm volatile("ldmatrix.sync.aligned.m8n8.x4.shared.b16 {%0,%1,%2,%3}, [%4];"
                 : "=r"(r0), "=r"(r1), "=r"(r2), "=r"(r3) : "r"(addr));
}
__device__ __forceinline__ void mma16816(float* c,
                                         uint32_t a0, uint32_t a1, uint32_t a2, uint32_t a3,
                                         uint32_t b0, uint32_t b1) {
    asm volatile("mma.sync.aligned.m16n8k16.row.col.f32.bf16.bf16.f32 "
                 "{%0,%1,%2,%3},{%4,%5,%6,%7},{%8,%9},{%0,%1,%2,%3};"
                 : "+f"(c[0]), "+f"(c[1]), "+f"(c[2]), "+f"(c[3])
                 : "r"(a0), "r"(a1), "r"(a2), "r"(a3), "r"(b0), "r"(b1));
}

// ------------------------------------------------------------------
// K_pre1: fp32 -> bf16 hi/lo split (row-major, same layout)
// ------------------------------------------------------------------
__global__ void split_act(const float* __restrict__ A,
                          __nv_bfloat16* __restrict__ Oh, __nv_bfloat16* __restrict__ Ol,
                          int n4)
{
    int i = blockIdx.x * 256 + threadIdx.x;
    if (i >= n4) return;
    float4 v = ((const float4*)A)[i];
    __nv_bfloat16 h0 = __float2bfloat16(v.x), h1 = __float2bfloat16(v.y);
    __nv_bfloat16 h2 = __float2bfloat16(v.z), h3 = __float2bfloat16(v.w);
    __nv_bfloat16 l0 = __float2bfloat16(v.x - __bfloat162float(h0));
    __nv_bfloat16 l1 = __float2bfloat16(v.y - __bfloat162float(h1));
    __nv_bfloat16 l2 = __float2bfloat16(v.z - __bfloat162float(h2));
    __nv_bfloat16 l3 = __float2bfloat16(v.w - __bfloat162float(h3));
    ((__nv_bfloat162*)Oh)[2*i]   = __halves2bfloat162(h0, h1);
    ((__nv_bfloat162*)Oh)[2*i+1] = __halves2bfloat162(h2, h3);
    ((__nv_bfloat162*)Ol)[2*i]   = __halves2bfloat162(l0, l1);
    ((__nv_bfloat162*)Ol)[2*i+1] = __halves2bfloat162(l2, l3);
}

// ------------------------------------------------------------------
// K_pre2: transpose + bf16 hi/lo split of weights.
// z=0: WE -> g_WEt*;  z=1..4: WA,WB,WV,WU -> g_Wct* rows (z-1)*512
// ------------------------------------------------------------------
__global__ void split_weights(const float* __restrict__ WE, const float* __restrict__ WA,
                              const float* __restrict__ WB, const float* __restrict__ WV,
                              const float* __restrict__ WU)
{
    __shared__ float tile[32][33];
    const int z = blockIdx.z;
    const float* W = (z == 0) ? WE : (z == 1) ? WA : (z == 2) ? WB : (z == 3) ? WV : WU;
    __nv_bfloat16* Oh = (z == 0) ? g_WEth : g_Wcth;
    __nv_bfloat16* Ol = (z == 0) ? g_WEtl : g_Wctl;
    const int nOff = (z == 0) ? 0 : (z - 1) * 512;
    const int k0 = blockIdx.x * 32, n0 = blockIdx.y * 32;
    const int tx = threadIdx.x & 31, ty = threadIdx.x >> 5;
#pragma unroll
    for (int q = 0; q < 4; q++)
        tile[ty + 8*q][tx] = W[(size_t)(k0 + ty + 8*q)*512 + n0 + tx];
    __syncthreads();
#pragma unroll
    for (int q = 0; q < 4; q++) {
        float f = tile[tx][ty + 8*q];
        __nv_bfloat16 h = __float2bfloat16(f);
        __nv_bfloat16 l = __float2bfloat16(f - __bfloat162float(h));
        size_t o = (size_t)(nOff + n0 + ty + 8*q)*512 + k0 + tx;
        Oh[o] = h; Ol[o] = l;
    }
}

// ------------------------------------------------------------------
// G: bf16x3 compensated GEMM on mma.sync (HMMA).
//   C[M x *] = A[M x 512] @ B ; A pre-split hi/lo row-major,
//   B pre-split/transposed [n][k] hi/lo.  CTA tile 128x128, BK=32.
// ------------------------------------------------------------------
__device__ __forceinline__ void load_stage(uint32_t s0, int tid, int row0, int n0, int M, int kt,
    const __nv_bfloat16* __restrict__ Ah, const __nv_bfloat16* __restrict__ Al,
    const __nv_bfloat16* __restrict__ Bh, const __nv_bfloat16* __restrict__ Bl)
{
#pragma unroll
    for (int q = 0; q < 2; q++) {
        int idx = tid + q*256;
        int r = idx >> 2, c = idx & 3;
        uint32_t doff = (uint32_t)r*SROWB + (uint32_t)c*16;
        int ar = row0 + r;
        bool av = ar < M;
        size_t agoff = (size_t)(av ? ar : 0)*512 + kt + c*8;
        cp_async16(s0 + doff,              Ah + agoff, av);
        cp_async16(s0 + ARR_BYTES + doff,  Al + agoff, av);
        size_t bgoff = (size_t)(n0 + r)*512 + kt + c*8;
        cp_async16(s0 + 2*ARR_BYTES + doff, Bh + bgoff, true);
        cp_async16(s0 + 3*ARR_BYTES + doff, Bl + bgoff, true);
    }
    asm volatile("cp.async.commit_group;" ::: "memory");
}

__device__ __forceinline__ void compute_stage(uint32_t s0, int lane, int wm, int wn,
                                              float acc[2][8][4])
{
#pragma unroll
    for (int s = 0; s < 2; s++) {
        uint32_t ah[2][4], al_[2][4], bh[4][4], bl[4][4];
#pragma unroll
        for (int f = 0; f < 2; f++) {
            uint32_t ra = s0 + (uint32_t)(wm*32 + f*16 + (lane & 15))*SROWB
                             + (uint32_t)((lane >> 4)*16 + s*32);
            ldsm4(ah[f][0], ah[f][1], ah[f][2], ah[f][3], ra);
            ldsm4(al_[f][0], al_[f][1], al_[f][2], al_[f][3], ra + ARR_BYTES);
        }
#pragma unroll
        for (int q = 0; q < 4; q++) {
            uint32_t rb = s0 + 2*ARR_BYTES + (uint32_t)(wn*64 + q*16 + (lane & 15))*SROWB
                             + (uint32_t)((lane >> 4)*16 + s*32);
            ldsm4(bh[q][0], bh[q][1], bh[q][2], bh[q][3], rb);
            ldsm4(bl[q][0], bl[q][1], bl[q][2], bl[q][3], rb + ARR_BYTES);
        }
#pragma unroll
        for (int f = 0; f < 2; f++)
#pragma unroll
            for (int q = 0; q < 4; q++) {
                mma16816(acc[f][2*q],   ah[f][0], ah[f][1], ah[f][2], ah[f][3], bh[q][0], bh[q][2]);
                mma16816(acc[f][2*q],   ah[f][0], ah[f][1], ah[f][2], ah[f][3], bl[q][0], bl[q][2]);
                mma16816(acc[f][2*q],   al_[f][0], al_[f][1], al_[f][2], al_[f][3], bh[q][0], bh[q][2]);
                mma16816(acc[f][2*q+1], ah[f][0], ah[f][1], ah[f][2], ah[f][3], bh[q][1], bh[q][3]);
                mma16816(acc[f][2*q+1], ah[f][0], ah[f][1], ah[f][2], ah[f][3], bl[q][1], bl[q][3]);
                mma16816(acc[f][2*q+1], al_[f][0], al_[f][1], al_[f][2], al_[f][3], bh[q][1], bh[q][3]);
            }
    }
}

__global__ __launch_bounds__(256, 1)
void gemm_bf16x3(const __nv_bfloat16* __restrict__ Ah, const __nv_bfloat16* __restrict__ Al, int M,
                 const __nv_bfloat16* __restrict__ Bh, const __nv_bfloat16* __restrict__ Bl,
                 float* __restrict__ C, int ldC)
{
    extern __shared__ char smem[];
    const uint32_t sb = smem_to_u32(smem);
    const int tid = threadIdx.x;
    const int lane = tid & 31, wid = tid >> 5;
    const int wm = wid >> 1, wn = wid & 1;
    const int row0 = blockIdx.x * BM;
    const int n0   = blockIdx.y * BN;

    float acc[2][8][4];
#pragma unroll
    for (int f = 0; f < 2; f++)
#pragma unroll
        for (int j = 0; j < 8; j++)
#pragma unroll
            for (int v = 0; v < 4; v++) acc[f][j][v] = 0.f;

    load_stage(sb, tid, row0, n0, M, 0, Ah, Al, Bh, Bl);

    for (int t = 0; t < 16; t++) {
        if (t + 1 < 16) {
            load_stage(sb + ((t+1) & 1)*STAGE_BYTES, tid, row0, n0, M, (t+1)*BK, Ah, Al, Bh, Bl);
            asm volatile("cp.async.wait_group 1;" ::: "memory");
        } else {
            asm volatile("cp.async.wait_group 0;" ::: "memory");
        }
        __syncthreads();
        compute_stage(sb + (t & 1)*STAGE_BYTES, lane, wm, wn, acc);
        __syncthreads();
    }

    // epilogue: each warp stores its 32x64 region
#pragma unroll
    for (int f = 0; f < 2; f++) {
        int rbase = row0 + wm*32 + f*16 + (lane >> 2);
#pragma unroll
        for (int h = 0; h < 2; h++) {
            int r = rbase + h*8;
            if (r < M) {
                float* dst = C + (size_t)r*ldC + n0 + wn*64 + (lane & 3)*2;
#pragma unroll
                for (int j = 0; j < 8; j++) {
                    float2 v = { acc[f][j][2*h], acc[f][j][2*h+1] };
                    *(float2*)&dst[j*8] = v;
                }
            }
        }
    }
}

// ------------------------------------------------------------------
// K_epi: per (b,i) CTA: e_lin + Vix + Vjx, LN, relu, residual,
// sigmoid, softmax over j, gated aggregation.
// ------------------------------------------------------------------
__global__ __launch_bounds__(256)
void edge_epilogue(const float* __restrict__ edge,
                   const float* __restrict__ ge, const float* __restrict__ be,
                   float* __restrict__ edge_out)
{
    extern __shared__ float sm[];
    float* sS   = sm;                 // [27][520]
    float* sVix = sm + 27*SSTR;
    float* sGe  = sVix + 512;
    float* sBe  = sGe + 512;

    const int tid = threadIdx.x;
    const int bi  = blockIdx.x;
    const int b   = bi / NNODE;
    const int i   = bi % NNODE;
    const size_t rowBaseE = (size_t)b*NNSQ + (size_t)i*NNODE;
    const float* eBase  = edge + rowBaseE*CDIM;
    const float* elBase = g_elin + rowBaseE*CDIM;

    {
        const float* vix = g_node + ((size_t)b*NNODE + i)*2048;   // Vix
        int c0 = tid, c1 = tid + 256;
        sVix[c0] = vix[c0]; sVix[c1] = vix[c1];
        sGe[c0]  = ge[c0];  sGe[c1]  = ge[c1];
        sBe[c0]  = be[c0];  sBe[c1]  = be[c1];
    }
#pragma unroll
    for (int l = 0; l < 14; l++) {
        int idx = tid + l*256;
        if (idx < 27*128) {
            int r = idx >> 7, c4 = idx & 127;
            *(float4*)&sS[r*SSTR + c4*4] = *(const float4*)&elBase[(size_t)r*512 + c4*4];
        }
    }
    __syncthreads();

    const int lane = tid & 31, wrp = tid >> 5;
    for (int r = wrp; r < NNODE; r += 8) {
        const float* vjx = g_node + ((size_t)b*NNODE + r)*2048 + 512;  // Vjx
        float v[16]; float s = 0.f, s2 = 0.f;
#pragma unroll
        for (int u = 0; u < 16; u++) {
            int c = lane + u*32;
            float t = sS[r*SSTR + c] + sVix[c] + vjx[c];
            v[u] = t; s += t; s2 += t*t;
        }
#pragma unroll
        for (int o = 16; o > 0; o >>= 1) {
            s  += __shfl_xor_sync(0xffffffffu, s,  o);
            s2 += __shfl_xor_sync(0xffffffffu, s2, o);
        }
        float mean = s * (1.f/512.f);
        float var  = s2 * (1.f/512.f) - mean*mean;
        float rstd = rsqrtf(var + 1e-5f);
        const float* eRow = eBase + (size_t)r*CDIM;
        float* oRow = edge_out + (rowBaseE + r)*CDIM;
#pragma unroll
        for (int u = 0; u < 16; u++) {
            int c = lane + u*32;
            float ln = (v[u] - mean)*rstd*sGe[c] + sBe[c];
            float eo = eRow[c] + fmaxf(ln, 0.f);
            oRow[c] = eo;
            sS[r*SSTR + c] = 1.f/(1.f + __expf(-eo));
        }
    }
    __syncthreads();

    float* aggRow = g_agg + ((size_t)b*NNODE + i)*CDIM;
#pragma unroll
    for (int h = 0; h < 2; h++) {
        int c = tid + h*256;
        float sum = 0.f, a = 0.f;
#pragma unroll
        for (int j = 0; j < NNODE; j++) {
            float ex = __expf(sS[j*SSTR + c]);
            sum += ex;
            a   += ex * g_node[((size_t)b*NNODE + j)*2048 + 1024 + c];   // Ujx
        }
        aggRow[c] = a / (sum * (float)NNODE);
    }
}

// ------------------------------------------------------------------
// K_fin: x_new = XU + agg; x_out = relu(x + LN(x_new))
// ------------------------------------------------------------------
__global__ void node_finalize(const float* __restrict__ x,
                              const float* __restrict__ gv, const float* __restrict__ bv,
                              float* __restrict__ x_out)
{
    __shared__ float rs[8], rs2[8];
    __shared__ float bmean, brstd;
    const int row = blockIdx.x;
    const int tid = threadIdx.x;
    const int lane = tid & 31, wrp = tid >> 5;
    const size_t base  = (size_t)row*CDIM;
    const size_t base2 = (size_t)row*2048 + 1536;   // XU

    float t0 = g_node[base2 + tid]       + g_agg[base + tid];
    float t1 = g_node[base2 + 256 + tid] + g_agg[base + 256 + tid];
    float s = t0 + t1, s2 = t0*t0 + t1*t1;
#pragma unroll
    for (int o = 16; o > 0; o >>= 1) {
        s  += __shfl_xor_sync(0xffffffffu, s,  o);
        s2 += __shfl_xor_sync(0xffffffffu, s2, o);
    }
    if (lane == 0) { rs[wrp] = s; rs2[wrp] = s2; }
    __syncthreads();
    if (tid == 0) {
        float S = 0.f, S2 = 0.f;
#pragma unroll
        for (int k = 0; k < 8; k++) { S += rs[k]; S2 += rs2[k]; }
        float mean = S * (1.f/512.f);
        float var  = S2 * (1.f/512.f) - mean*mean;
        bmean = mean; brstd = rsqrtf(var + 1e-5f);
    }
    __syncthreads();
    float mean = bmean, rstd = brstd;
    int c0 = tid, c1 = tid + 256;
    float ln0 = (t0 - mean)*rstd*gv[c0] + bv[c0];
    float ln1 = (t1 - mean)*rstd*gv[c1] + bv[c1];
    x_out[base + c0] = fmaxf(x[base + c0] + ln0, 0.f);
    x_out[base + c1] = fmaxf(x[base + c1] + ln1, 0.f);
}

// ------------------------------------------------------------------
extern "C" void kernel_launch(void* const* d_in, const int* in_sizes, int n_in,
                              void* d_out, int out_size)
{
    const float* x    = (const float*)d_in[0];
    const float* edge = (const float*)d_in[1];
    const float* WA   = (const float*)d_in[2];
    const float* WB   = (const float*)d_in[3];
    const float* WE   = (const float*)d_in[4];
    const float* WU   = (const float*)d_in[5];
    const float* WV   = (const float*)d_in[6];
    const float* gv   = (const float*)d_in[7];
    const float* bv   = (const float*)d_in[8];
    const float* ge   = (const float*)d_in[9];
    const float* be   = (const float*)d_in[10];

    float* x_out = (float*)d_out;
    float* e_out = (float*)d_out + (size_t)NROWS_X*CDIM;

    cudaFuncSetAttribute(gemm_bf16x3, cudaFuncAttributeMaxDynamicSharedMemorySize, SMEM_GEMM);
    cudaFuncSetAttribute(edge_epilogue, cudaFuncAttributeMaxDynamicSharedMemorySize,
                         (27*SSTR + 1536) * (int)sizeof(float));

    float *d_elin;
    __nv_bfloat16 *d_eAh, *d_eAl, *d_xAh, *d_xAl, *d_WEth, *d_WEtl, *d_Wcth, *d_Wctl;
    float *d_node;
    cudaGetSymbolAddress((void**)&d_elin, g_elin);
    cudaGetSymbolAddress((void**)&d_node, g_node);
    cudaGetSymbolAddress((void**)&d_eAh, g_eAh);
    cudaGetSymbolAddress((void**)&d_eAl, g_eAl);
    cudaGetSymbolAddress((void**)&d_xAh, g_xAh);
    cudaGetSymbolAddress((void**)&d_xAl, g_xAl);
    cudaGetSymbolAddress((void**)&d_WEth, g_WEth);
    cudaGetSymbolAddress((void**)&d_WEtl, g_WEtl);
    cudaGetSymbolAddress((void**)&d_Wcth, g_Wcth);
    cudaGetSymbolAddress((void**)&d_Wctl, g_Wctl);

    // activation + weight splits
    split_act<<<(NROWS_E*CDIM/4 + 255)/256, 256>>>(edge, d_eAh, d_eAl, NROWS_E*CDIM/4);
    split_act<<<(NROWS_X*CDIM/4 + 255)/256, 256>>>(x, d_xAh, d_xAl, NROWS_X*CDIM/4);
    split_weights<<<dim3(16, 16, 5), 256>>>(WE, WA, WB, WV, WU);

    // node GEMM: x(1728x512) @ [WA|WB|WV|WU](512x2048) -> g_node
    gemm_bf16x3<<<dim3(14, 16), 256, SMEM_GEMM>>>(d_xAh, d_xAl, NROWS_X, d_Wcth, d_Wctl, d_node, 2048);
    // edge GEMM: edge(46656x512) @ WE(512x512) -> g_elin
    gemm_bf16x3<<<dim3(365, 4), 256, SMEM_GEMM>>>(d_eAh, d_eAl, NROWS_E, d_WEth, d_WEtl, d_elin, 512);

    edge_epilogue<<<BATCH*NNODE, 256, (27*SSTR + 1536)*sizeof(float)>>>(edge, ge, be, e_out);
    node_finalize<<<NROWS_X, 256>>>(x, gv, bv, x_out);
}